// round 1
// baseline (speedup 1.0000x reference)
#include <cuda_runtime.h>
#include <cuda_bf16.h>

// Problem constants
#define Bq   2
#define Tq   2048
#define Dq   1024
#define Hq   16
#define DKq  64          // D / H
#define Mq   (Bq*Tq)     // 4096 rows for projections

// ---------------- scratch (device globals: allocation-free) ----------------
__device__ float g_Q[Mq * Dq];
__device__ float g_K[Mq * Dq];
__device__ float g_V[Mq * Dq];
__device__ float g_AO[Mq * Dq];   // attention output before Wo

// ---------------------------------------------------------------------------
// GEMM: C[M,N] = A[M,K] @ W[K,N] + bias[N]      (fp32, 128x128x8 tiles)
// grid  = (N/128, M/128), block = 256 threads, 8x8 per-thread microtile
// ---------------------------------------------------------------------------
__global__ void __launch_bounds__(256, 2)
gemm_bias_kernel(const float* __restrict__ A, const float* __restrict__ W,
                 const float* __restrict__ bias, float* __restrict__ C,
                 int M, int N, int K)
{
    __shared__ float As[8][132];   // [k][m] transposed, padded
    __shared__ float Bs[8][132];   // [k][n], padded

    const int t  = threadIdx.x;
    const int tx = t & 15;         // 0..15 -> 8 cols each
    const int ty = t >> 4;         // 0..15 -> 8 rows each
    const int m0 = blockIdx.y * 128;
    const int n0 = blockIdx.x * 128;

    const int arow = t >> 1;          // 0..127
    const int aseg = (t & 1) * 4;     // 0 or 4
    const int brow = t >> 5;          // 0..7
    const int bcol = (t & 31) * 4;    // 0..124

    float acc[8][8];
#pragma unroll
    for (int i = 0; i < 8; i++)
#pragma unroll
        for (int j = 0; j < 8; j++) acc[i][j] = 0.f;

    for (int k0 = 0; k0 < K; k0 += 8) {
        float4 av = *(const float4*)(A + (size_t)(m0 + arow) * K + k0 + aseg);
        As[aseg + 0][arow] = av.x;
        As[aseg + 1][arow] = av.y;
        As[aseg + 2][arow] = av.z;
        As[aseg + 3][arow] = av.w;

        float4 bv = *(const float4*)(W + (size_t)(k0 + brow) * N + n0 + bcol);
        *(float4*)&Bs[brow][bcol] = bv;

        __syncthreads();

#pragma unroll
        for (int kk = 0; kk < 8; kk++) {
            float a[8], b[8];
            *(float4*)(a)     = *(const float4*)&As[kk][ty * 8];
            *(float4*)(a + 4) = *(const float4*)&As[kk][ty * 8 + 4];
            *(float4*)(b)     = *(const float4*)&Bs[kk][tx * 8];
            *(float4*)(b + 4) = *(const float4*)&Bs[kk][tx * 8 + 4];
#pragma unroll
            for (int i = 0; i < 8; i++)
#pragma unroll
                for (int j = 0; j < 8; j++)
                    acc[i][j] = fmaf(a[i], b[j], acc[i][j]);
        }
        __syncthreads();
    }

    // epilogue: bias + store (vectorized)
#pragma unroll
    for (int i = 0; i < 8; i++) {
        const size_t r = (size_t)(m0 + ty * 8 + i);
        float* cp = C + r * N + n0 + tx * 8;
        const float* bp = bias + n0 + tx * 8;
        float4 o0, o1;
        o0.x = acc[i][0] + bp[0]; o0.y = acc[i][1] + bp[1];
        o0.z = acc[i][2] + bp[2]; o0.w = acc[i][3] + bp[3];
        o1.x = acc[i][4] + bp[4]; o1.y = acc[i][5] + bp[5];
        o1.z = acc[i][6] + bp[6]; o1.w = acc[i][7] + bp[7];
        *(float4*)(cp)     = o0;
        *(float4*)(cp + 4) = o1;
    }
}

// ---------------------------------------------------------------------------
// Flash-attention (causal). One CTA per (query-tile of 64, b*h).
// Q/K/V in [B,T,D] layout; head h uses columns [h*64, h*64+64).
// 256 threads as 16x16 grid; each thread owns a 4x4 score / output microtile.
// Online softmax with row stats replicated across the 16 tx-threads of a row
// group (kept consistent by identical shuffle reductions).
// ---------------------------------------------------------------------------
#define PAD 65   // 64 + 1 padding
__global__ void __launch_bounds__(256, 2)
attn_kernel(const float* __restrict__ Q, const float* __restrict__ K,
            const float* __restrict__ V, float* __restrict__ O)
{
    extern __shared__ float sm[];
    float* Qs = sm;                 // 64 x 65
    float* Ks = Qs + 64 * PAD;      // 64 x 65
    float* Vs = Ks + 64 * PAD;      // 64 x 65
    float* Ps = Vs + 64 * PAD;      // 64 x 65

    const int qt = blockIdx.x;              // query tile (0..31)
    const int bh = blockIdx.y;              // b*H + h
    const int b  = bh / Hq;
    const int h  = bh % Hq;

    const int t  = threadIdx.x;
    const int tx = t & 15;
    const int ty = t >> 4;

    const float* Qbase = Q + ((size_t)b * Tq + qt * 64) * Dq + h * DKq;

    // load Q tile, pre-scaled by 1/sqrt(DK) = 1/8
#pragma unroll
    for (int idx = t; idx < 64 * 16; idx += 256) {
        int row = idx >> 4;
        int c4  = (idx & 15) * 4;
        float4 v = *(const float4*)(Qbase + (size_t)row * Dq + c4);
        float* dst = &Qs[row * PAD + c4];
        dst[0] = v.x * 0.125f; dst[1] = v.y * 0.125f;
        dst[2] = v.z * 0.125f; dst[3] = v.w * 0.125f;
    }

    float m[4], l[4], o[4][4];
#pragma unroll
    for (int i = 0; i < 4; i++) {
        m[i] = -1e30f; l[i] = 0.f;
#pragma unroll
        for (int j = 0; j < 4; j++) o[i][j] = 0.f;
    }

    for (int jt = 0; jt <= qt; jt++) {
        // load K and V tiles
        const float* Kb = K + ((size_t)b * Tq + jt * 64) * Dq + h * DKq;
        const float* Vb = V + ((size_t)b * Tq + jt * 64) * Dq + h * DKq;
#pragma unroll
        for (int idx = t; idx < 64 * 16; idx += 256) {
            int row = idx >> 4;
            int c4  = (idx & 15) * 4;
            float4 kv = *(const float4*)(Kb + (size_t)row * Dq + c4);
            float4 vv = *(const float4*)(Vb + (size_t)row * Dq + c4);
            float* kd = &Ks[row * PAD + c4];
            float* vd = &Vs[row * PAD + c4];
            kd[0] = kv.x; kd[1] = kv.y; kd[2] = kv.z; kd[3] = kv.w;
            vd[0] = vv.x; vd[1] = vv.y; vd[2] = vv.z; vd[3] = vv.w;
        }
        __syncthreads();

        // S (4x4 per thread) = Q[ty*4..][*] . K[tx*4..][*]
        float s[4][4];
#pragma unroll
        for (int i = 0; i < 4; i++)
#pragma unroll
            for (int j = 0; j < 4; j++) s[i][j] = 0.f;

#pragma unroll 8
        for (int d = 0; d < 64; d++) {
            float qv[4], kv[4];
#pragma unroll
            for (int i = 0; i < 4; i++) qv[i] = Qs[(ty * 4 + i) * PAD + d];
#pragma unroll
            for (int j = 0; j < 4; j++) kv[j] = Ks[(tx * 4 + j) * PAD + d];
#pragma unroll
            for (int i = 0; i < 4; i++)
#pragma unroll
                for (int j = 0; j < 4; j++)
                    s[i][j] = fmaf(qv[i], kv[j], s[i][j]);
        }

        // causal mask on the diagonal tile
        if (jt == qt) {
#pragma unroll
            for (int i = 0; i < 4; i++)
#pragma unroll
                for (int j = 0; j < 4; j++)
                    if (tx * 4 + j > ty * 4 + i) s[i][j] = -1e30f;
        }

        // online softmax per row (reduce across the 16 tx threads, same half-warp)
#pragma unroll
        for (int i = 0; i < 4; i++) {
            float mx = fmaxf(fmaxf(s[i][0], s[i][1]), fmaxf(s[i][2], s[i][3]));
#pragma unroll
            for (int off = 1; off < 16; off <<= 1)
                mx = fmaxf(mx, __shfl_xor_sync(0xffffffffu, mx, off));
            float mnew  = fmaxf(m[i], mx);
            float alpha = __expf(m[i] - mnew);
            m[i] = mnew;

            float rs = 0.f;
#pragma unroll
            for (int j = 0; j < 4; j++) {
                s[i][j] = __expf(s[i][j] - mnew);
                rs += s[i][j];
            }
#pragma unroll
            for (int off = 1; off < 16; off <<= 1)
                rs += __shfl_xor_sync(0xffffffffu, rs, off);
            l[i] = l[i] * alpha + rs;

#pragma unroll
            for (int j = 0; j < 4; j++) {
                o[i][j] *= alpha;
                Ps[(ty * 4 + i) * PAD + tx * 4 + j] = s[i][j];
            }
        }
        __syncthreads();

        // O += P @ V  (P: 64x64, V: 64x64)
#pragma unroll 8
        for (int c = 0; c < 64; c++) {
            float pv[4], vv[4];
#pragma unroll
            for (int i = 0; i < 4; i++) pv[i] = Ps[(ty * 4 + i) * PAD + c];
#pragma unroll
            for (int j = 0; j < 4; j++) vv[j] = Vs[c * PAD + tx * 4 + j];
#pragma unroll
            for (int i = 0; i < 4; i++)
#pragma unroll
                for (int j = 0; j < 4; j++)
                    o[i][j] = fmaf(pv[i], vv[j], o[i][j]);
        }
        __syncthreads();   // protect Ks/Vs before next tile's load
    }

    // write normalized output
    float* Ob = O + ((size_t)b * Tq + qt * 64) * Dq + h * DKq;
#pragma unroll
    for (int i = 0; i < 4; i++) {
        float inv = 1.0f / l[i];
#pragma unroll
        for (int j = 0; j < 4; j++)
            Ob[(size_t)(ty * 4 + i) * Dq + tx * 4 + j] = o[i][j] * inv;
    }
}

// ---------------------------------------------------------------------------
extern "C" void kernel_launch(void* const* d_in, const int* in_sizes, int n_in,
                              void* d_out, int out_size)
{
    const float* x  = (const float*)d_in[0];
    // d_in[1] = mask (causal tril, applied analytically)
    const float* Wq = (const float*)d_in[2];
    const float* bq = (const float*)d_in[3];
    const float* Wk = (const float*)d_in[4];
    const float* bk = (const float*)d_in[5];
    const float* Wv = (const float*)d_in[6];
    const float* bv = (const float*)d_in[7];
    const float* Wo = (const float*)d_in[8];
    const float* bo = (const float*)d_in[9];
    float* out = (float*)d_out;

    float *qp, *kp, *vp, *aop;
    cudaGetSymbolAddress((void**)&qp,  g_Q);
    cudaGetSymbolAddress((void**)&kp,  g_K);
    cudaGetSymbolAddress((void**)&vp,  g_V);
    cudaGetSymbolAddress((void**)&aop, g_AO);

    const int smem_attn = 4 * 64 * PAD * sizeof(float);   // 66560 B
    cudaFuncSetAttribute(attn_kernel,
                         cudaFuncAttributeMaxDynamicSharedMemorySize, smem_attn);

    dim3 gblk(256);
    dim3 ggrid(Dq / 128, Mq / 128);   // (8, 32)

    gemm_bias_kernel<<<ggrid, gblk>>>(x, Wq, bq, qp, Mq, Dq, Dq);
    gemm_bias_kernel<<<ggrid, gblk>>>(x, Wk, bk, kp, Mq, Dq, Dq);
    gemm_bias_kernel<<<ggrid, gblk>>>(x, Wv, bv, vp, Mq, Dq, Dq);

    dim3 agrid(Tq / 64, Bq * Hq);     // (32, 32)
    attn_kernel<<<agrid, 256, smem_attn>>>(qp, kp, vp, aop);

    gemm_bias_kernel<<<ggrid, gblk>>>(aop, Wo, bo, out, Mq, Dq, Dq);
}

// round 3
// speedup vs baseline: 1.2930x; 1.2930x over previous
#include <cuda_runtime.h>
#include <cuda_bf16.h>
#include <cstdint>
#include <cstddef>

// Problem constants
#define Bq   2
#define Tq   2048
#define Dq   1024
#define Hq   16
#define DKq  64
#define Mq   (Bq*Tq)     // 4096

// ---------------- scratch (device globals: allocation-free) ----------------
__device__ float g_Q[Mq * Dq];
__device__ float g_K[Mq * Dq];
__device__ float g_V[Mq * Dq];
__device__ float g_AO[Mq * Dq];
__device__ __align__(16) __nv_bfloat16 g_Ahi[Mq * Dq];
__device__ __align__(16) __nv_bfloat16 g_Alo[Mq * Dq];
__device__ __align__(16) __nv_bfloat16 g_Whi[4][Dq * Dq];   // transposed: [n][k]
__device__ __align__(16) __nv_bfloat16 g_Wlo[4][Dq * Dq];

// ---------------------------------------------------------------------------
__device__ __forceinline__ uint32_t smem_u32(const void* p) {
    uint32_t a;
    asm("{ .reg .u64 t; cvta.to.shared.u64 t, %1; cvt.u32.u64 %0, t; }" : "=r"(a) : "l"(p));
    return a;
}
__device__ __forceinline__ void cp_async16(uint32_t saddr, const void* gaddr) {
    asm volatile("cp.async.cg.shared.global [%0], [%1], 16;" :: "r"(saddr), "l"(gaddr));
}
__device__ __forceinline__ void ldsm_x4(uint32_t* r, uint32_t saddr) {
    asm volatile("ldmatrix.sync.aligned.m8n8.x4.shared.b16 {%0,%1,%2,%3}, [%4];"
                 : "=r"(r[0]), "=r"(r[1]), "=r"(r[2]), "=r"(r[3]) : "r"(saddr));
}
__device__ __forceinline__ void mma16816(float* d, const uint32_t* a, uint32_t b0, uint32_t b1) {
    asm volatile(
        "mma.sync.aligned.m16n8k16.row.col.f32.bf16.bf16.f32 "
        "{%0,%1,%2,%3}, {%4,%5,%6,%7}, {%8,%9}, {%0,%1,%2,%3};"
        : "+f"(d[0]), "+f"(d[1]), "+f"(d[2]), "+f"(d[3])
        : "r"(a[0]), "r"(a[1]), "r"(a[2]), "r"(a[3]), "r"(b0), "r"(b1));
}

// ---------------------------------------------------------------------------
// fp32 -> bf16 hi/lo split (elementwise)
// ---------------------------------------------------------------------------
__global__ void split_kernel(const float* __restrict__ src,
                             __nv_bfloat16* __restrict__ hi,
                             __nv_bfloat16* __restrict__ lo, int n)
{
    int i = (blockIdx.x * blockDim.x + threadIdx.x) * 4;
    if (i >= n) return;
    float4 v = *(const float4*)(src + i);
    __nv_bfloat16 h0 = __float2bfloat16(v.x), h1 = __float2bfloat16(v.y);
    __nv_bfloat16 h2 = __float2bfloat16(v.z), h3 = __float2bfloat16(v.w);
    __nv_bfloat16 l0 = __float2bfloat16(v.x - __bfloat162float(h0));
    __nv_bfloat16 l1 = __float2bfloat16(v.y - __bfloat162float(h1));
    __nv_bfloat16 l2 = __float2bfloat16(v.z - __bfloat162float(h2));
    __nv_bfloat16 l3 = __float2bfloat16(v.w - __bfloat162float(h3));
    ((__nv_bfloat162*)(hi + i))[0] = __halves2bfloat162(h0, h1);
    ((__nv_bfloat162*)(hi + i))[1] = __halves2bfloat162(h2, h3);
    ((__nv_bfloat162*)(lo + i))[0] = __halves2bfloat162(l0, l1);
    ((__nv_bfloat162*)(lo + i))[1] = __halves2bfloat162(l2, l3);
}

// ---------------------------------------------------------------------------
// W[k][n] fp32 -> Wt_hi/lo[n][k] bf16 (transposed split)
// ---------------------------------------------------------------------------
__global__ void transpose_split_kernel(const float* __restrict__ W,
                                       __nv_bfloat16* __restrict__ hi,
                                       __nv_bfloat16* __restrict__ lo)
{
    __shared__ float tile[32][33];
    int n0 = blockIdx.x * 32, k0 = blockIdx.y * 32;
    int x = threadIdx.x, y = threadIdx.y;  // 32 x 8
#pragma unroll
    for (int r = 0; r < 32; r += 8)
        tile[y + r][x] = W[(size_t)(k0 + y + r) * Dq + n0 + x];
    __syncthreads();
#pragma unroll
    for (int r = 0; r < 32; r += 8) {
        float v = tile[x][y + r];  // = W[k0+x][n0+y+r]
        __nv_bfloat16 h = __float2bfloat16(v);
        hi[(size_t)(n0 + y + r) * Dq + k0 + x] = h;
        lo[(size_t)(n0 + y + r) * Dq + k0 + x] = __float2bfloat16(v - __bfloat162float(h));
    }
}

// ---------------------------------------------------------------------------
// mma.sync GEMM: C[4096,1024] = (Ahi+Alo) @ (Bhi+Blo)^T + bias
// 3-pass bf16 split: Ah*Bh + Ah*Bl + Al*Bh  (fp32 accumulate)
// Block 128x128, 8 warps (warp tile 64x32), BK=32, 3-stage cp.async pipeline.
// smem per stage: A 128x(32+8pad) halves (80B row stride) + B same = 20480B.
// ---------------------------------------------------------------------------
#define GSTAGE 20480
#define GEMM_SMEM (3 * GSTAGE)

__global__ void __launch_bounds__(256, 2)
gemm_mma(const __nv_bfloat16* __restrict__ Ah, const __nv_bfloat16* __restrict__ Al,
         const __nv_bfloat16* __restrict__ Bh, const __nv_bfloat16* __restrict__ Bl,
         const float* __restrict__ bias, float* __restrict__ C)
{
    extern __shared__ char smc[];
    const uint32_t smb = smem_u32(smc);
    const int t = threadIdx.x, lane = t & 31, wid = t >> 5;
    const int wm = wid >> 2, wn = wid & 3;           // 2 x 4 warp grid
    const int m0 = blockIdx.y * 128, n0 = blockIdx.x * 128;

    float acc[4][4][4];
#pragma unroll
    for (int i = 0; i < 4; i++)
#pragma unroll
        for (int j = 0; j < 4; j++)
#pragma unroll
            for (int k = 0; k < 4; k++) acc[i][j][k] = 0.f;

    const __nv_bfloat16* Asrc[3] = { Ah + (size_t)m0 * Dq, Ah + (size_t)m0 * Dq,
                                     Al + (size_t)m0 * Dq };
    const __nv_bfloat16* Bsrc[3] = { Bh + (size_t)n0 * Dq, Bl + (size_t)n0 * Dq,
                                     Bh + (size_t)n0 * Dq };

    // copy indices for this thread: 2 x 16B for A, 2 x 16B for B per chunk
    const int r0c = t >> 1, s0c = (t & 1) * 2;        // idx pattern: 512 copies / 256 thr

    auto issue = [&](int c) {
        const int st = c % 3, pass = c >> 5, kk = (c & 31) * 32;
        const uint32_t abase = smb + st * GSTAGE;
        const uint32_t bbase = abase + 10240;
        const __nv_bfloat16* As = Asrc[pass] + kk;
        const __nv_bfloat16* Bs = Bsrc[pass] + kk;
#pragma unroll
        for (int it = 0; it < 2; ++it) {
            int r = r0c, seg = s0c + it;
            cp_async16(abase + r * 80 + seg * 16, As + (size_t)r * Dq + seg * 8);
            cp_async16(bbase + r * 80 + seg * 16, Bs + (size_t)r * Dq + seg * 8);
        }
        asm volatile("cp.async.commit_group;" ::: "memory");
    };

    issue(0);
    issue(1);

    for (int c = 0; c < 96; ++c) {
        if (c < 94) asm volatile("cp.async.wait_group 1;" ::: "memory");
        else        asm volatile("cp.async.wait_group 0;" ::: "memory");
        __syncthreads();

        if (c + 2 < 96) issue(c + 2);

        const int st = c % 3;
        const uint32_t abase = smb + st * GSTAGE;
        const uint32_t bbase = abase + 10240;

#pragma unroll
        for (int ks = 0; ks < 2; ++ks) {
            uint32_t a[4][4], b[2][4];
#pragma unroll
            for (int mi = 0; mi < 4; ++mi) {
                int row  = wm * 64 + mi * 16 + (lane & 15);
                int colh = ks * 16 + (lane >> 4) * 8;
                ldsm_x4(a[mi], abase + row * 80 + colh * 2);
            }
#pragma unroll
            for (int g = 0; g < 2; ++g) {
                int row  = wn * 32 + g * 16 + ((lane >> 4) & 1) * 8 + (lane & 7);
                int colh = ks * 16 + ((lane >> 3) & 1) * 8;
                ldsm_x4(b[g], bbase + row * 80 + colh * 2);
            }
#pragma unroll
            for (int mi = 0; mi < 4; ++mi)
#pragma unroll
                for (int ni = 0; ni < 4; ++ni)
                    mma16816(acc[mi][ni], a[mi],
                             b[ni >> 1][(ni & 1) * 2], b[ni >> 1][(ni & 1) * 2 + 1]);
        }
        __syncthreads();
    }

    // epilogue: bias + store
#pragma unroll
    for (int mi = 0; mi < 4; ++mi) {
#pragma unroll
        for (int ni = 0; ni < 4; ++ni) {
            int row = m0 + wm * 64 + mi * 16 + (lane >> 2);
            int col = n0 + wn * 32 + ni * 8 + (lane & 3) * 2;
            float b0 = bias[col], b1 = bias[col + 1];
            float2 v0 = { acc[mi][ni][0] + b0, acc[mi][ni][1] + b1 };
            float2 v1 = { acc[mi][ni][2] + b0, acc[mi][ni][3] + b1 };
            *(float2*)(C + (size_t)row * Dq + col)       = v0;
            *(float2*)(C + (size_t)(row + 8) * Dq + col) = v1;
        }
    }
}

// ---------------------------------------------------------------------------
// Flash attention (causal), vectorized smem layout.
// Qt/Kt stored [d][row] (transposed), Vs [row][d], Pt [key][query].
// ---------------------------------------------------------------------------
#define APAD 68
#define ATTN_SMEM (4 * 64 * APAD * 4)

__global__ void __launch_bounds__(256, 2)
attn_kernel(const float* __restrict__ Q, const float* __restrict__ K,
            const float* __restrict__ V, float* __restrict__ O)
{
    extern __shared__ float smf[];
    float* Qt = smf;                  // [64 d][APAD]
    float* Kt = Qt + 64 * APAD;       // [64 d][APAD]
    float* Vs = Kt + 64 * APAD;       // [64 row][APAD]
    float* Pt = Vs + 64 * APAD;       // [64 key][APAD]

    const int qt = blockIdx.x, bh = blockIdx.y;
    const int b = bh >> 4, h = bh & 15;
    const int t = threadIdx.x, tx = t & 15, ty = t >> 4;

    const float* Qb = Q + ((size_t)b * Tq + qt * 64) * Dq + h * DKq;
#pragma unroll
    for (int it = 0; it < 4; ++it) {
        int idx = t + it * 256;
        int row = idx >> 4, c4 = (idx & 15) * 4;
        float4 v = *(const float4*)(Qb + (size_t)row * Dq + c4);
        Qt[(c4 + 0) * APAD + row] = v.x * 0.125f;
        Qt[(c4 + 1) * APAD + row] = v.y * 0.125f;
        Qt[(c4 + 2) * APAD + row] = v.z * 0.125f;
        Qt[(c4 + 3) * APAD + row] = v.w * 0.125f;
    }

    float m[4], l[4], o[4][4];
#pragma unroll
    for (int i = 0; i < 4; i++) {
        m[i] = -1e30f; l[i] = 0.f;
#pragma unroll
        for (int j = 0; j < 4; j++) o[i][j] = 0.f;
    }

    for (int jt = 0; jt <= qt; ++jt) {
        const float* Kb = K + ((size_t)b * Tq + jt * 64) * Dq + h * DKq;
        const float* Vb = V + ((size_t)b * Tq + jt * 64) * Dq + h * DKq;
#pragma unroll
        for (int it = 0; it < 4; ++it) {
            int idx = t + it * 256;
            int row = idx >> 4, c4 = (idx & 15) * 4;
            float4 kv = *(const float4*)(Kb + (size_t)row * Dq + c4);
            Kt[(c4 + 0) * APAD + row] = kv.x;
            Kt[(c4 + 1) * APAD + row] = kv.y;
            Kt[(c4 + 2) * APAD + row] = kv.z;
            Kt[(c4 + 3) * APAD + row] = kv.w;
            float4 vv = *(const float4*)(Vb + (size_t)row * Dq + c4);
            *(float4*)&Vs[row * APAD + c4] = vv;
        }
        __syncthreads();

        float s[4][4];
#pragma unroll
        for (int i = 0; i < 4; i++)
#pragma unroll
            for (int j = 0; j < 4; j++) s[i][j] = 0.f;

#pragma unroll 4
        for (int d = 0; d < 64; ++d) {
            float qa[4], ka[4];
            *(float4*)qa = *(const float4*)&Qt[d * APAD + ty * 4];
            *(float4*)ka = *(const float4*)&Kt[d * APAD + tx * 4];
#pragma unroll
            for (int i = 0; i < 4; i++)
#pragma unroll
                for (int j = 0; j < 4; j++)
                    s[i][j] = fmaf(qa[i], ka[j], s[i][j]);
        }

        if (jt == qt) {
#pragma unroll
            for (int i = 0; i < 4; i++)
#pragma unroll
                for (int j = 0; j < 4; j++)
                    if (tx * 4 + j > ty * 4 + i) s[i][j] = -1e30f;
        }

#pragma unroll
        for (int i = 0; i < 4; i++) {
            float mx = fmaxf(fmaxf(s[i][0], s[i][1]), fmaxf(s[i][2], s[i][3]));
#pragma unroll
            for (int off = 1; off < 16; off <<= 1)
                mx = fmaxf(mx, __shfl_xor_sync(0xffffffffu, mx, off));
            float mnew = fmaxf(m[i], mx);
            float alpha = __expf(m[i] - mnew);
            m[i] = mnew;

            float rs = 0.f;
#pragma unroll
            for (int j = 0; j < 4; j++) {
                s[i][j] = __expf(s[i][j] - mnew);
                rs += s[i][j];
            }
#pragma unroll
            for (int off = 1; off < 16; off <<= 1)
                rs += __shfl_xor_sync(0xffffffffu, rs, off);
            l[i] = l[i] * alpha + rs;

#pragma unroll
            for (int j = 0; j < 4; j++) {
                o[i][j] *= alpha;
                Pt[(tx * 4 + j) * APAD + ty * 4 + i] = s[i][j];
            }
        }
        __syncthreads();

#pragma unroll 4
        for (int c = 0; c < 64; ++c) {
            float pa[4], va[4];
            *(float4*)pa = *(const float4*)&Pt[c * APAD + ty * 4];
            *(float4*)va = *(const float4*)&Vs[c * APAD + tx * 4];
#pragma unroll
            for (int i = 0; i < 4; i++)
#pragma unroll
                for (int j = 0; j < 4; j++)
                    o[i][j] = fmaf(pa[i], va[j], o[i][j]);
        }
        __syncthreads();
    }

    float* Ob = O + ((size_t)b * Tq + qt * 64) * Dq + h * DKq;
#pragma unroll
    for (int i = 0; i < 4; i++) {
        float inv = 1.0f / l[i];
#pragma unroll
        for (int j = 0; j < 4; j++)
            Ob[(size_t)(ty * 4 + i) * Dq + tx * 4 + j] = o[i][j] * inv;
    }
}

// ---------------------------------------------------------------------------
extern "C" void kernel_launch(void* const* d_in, const int* in_sizes, int n_in,
                              void* d_out, int out_size)
{
    const float* x  = (const float*)d_in[0];
    const float* Wq = (const float*)d_in[2];
    const float* bq = (const float*)d_in[3];
    const float* Wk = (const float*)d_in[4];
    const float* bk = (const float*)d_in[5];
    const float* Wv = (const float*)d_in[6];
    const float* bv = (const float*)d_in[7];
    const float* Wo = (const float*)d_in[8];
    const float* bo = (const float*)d_in[9];
    float* out = (float*)d_out;

    float *qp, *kp, *vp, *aop;
    __nv_bfloat16 *ahi, *alo, *whi, *wlo;
    cudaGetSymbolAddress((void**)&qp,  g_Q);
    cudaGetSymbolAddress((void**)&kp,  g_K);
    cudaGetSymbolAddress((void**)&vp,  g_V);
    cudaGetSymbolAddress((void**)&aop, g_AO);
    cudaGetSymbolAddress((void**)&ahi, g_Ahi);
    cudaGetSymbolAddress((void**)&alo, g_Alo);
    cudaGetSymbolAddress((void**)&whi, g_Whi);
    cudaGetSymbolAddress((void**)&wlo, g_Wlo);

    cudaFuncSetAttribute(gemm_mma, cudaFuncAttributeMaxDynamicSharedMemorySize, GEMM_SMEM);
    cudaFuncSetAttribute(attn_kernel, cudaFuncAttributeMaxDynamicSharedMemorySize, ATTN_SMEM);

    const int NPROJ = Mq * Dq;
    dim3 tsg(32, 32), tsb(32, 8);
    dim3 ggrid(Dq / 128, Mq / 128);      // (8, 32)

    // 1) split x, transpose+split weights
    split_kernel<<<NPROJ / 1024, 256>>>(x, ahi, alo, NPROJ);
    const float* Ws[4] = { Wq, Wk, Wv, Wo };
    for (int w = 0; w < 4; ++w)
        transpose_split_kernel<<<tsg, tsb>>>(Ws[w], whi + (size_t)w * Dq * Dq,
                                             wlo + (size_t)w * Dq * Dq);

    // 2) Q/K/V projections (tensor core, 3-pass bf16 split)
    gemm_mma<<<ggrid, 256, GEMM_SMEM>>>(ahi, alo, whi + 0 * (size_t)Dq * Dq,
                                        wlo + 0 * (size_t)Dq * Dq, bq, qp);
    gemm_mma<<<ggrid, 256, GEMM_SMEM>>>(ahi, alo, whi + 1 * (size_t)Dq * Dq,
                                        wlo + 1 * (size_t)Dq * Dq, bk, kp);
    gemm_mma<<<ggrid, 256, GEMM_SMEM>>>(ahi, alo, whi + 2 * (size_t)Dq * Dq,
                                        wlo + 2 * (size_t)Dq * Dq, bv, vp);

    // 3) attention
    dim3 agrid(Tq / 64, Bq * Hq);
    attn_kernel<<<agrid, 256, ATTN_SMEM>>>(qp, kp, vp, aop);

    // 4) output projection
    split_kernel<<<NPROJ / 1024, 256>>>(aop, ahi, alo, NPROJ);
    gemm_mma<<<ggrid, 256, GEMM_SMEM>>>(ahi, alo, whi + 3 * (size_t)Dq * Dq,
                                        wlo + 3 * (size_t)Dq * Dq, bo, out);
}

// round 4
// speedup vs baseline: 2.1675x; 1.6763x over previous
#include <cuda_runtime.h>
#include <cuda_bf16.h>
#include <cstdint>
#include <cstddef>

// Problem constants
#define Bq   2
#define Tq   2048
#define Dq   1024
#define Hq   16
#define DKq  64
#define Mq   (Bq*Tq)     // 4096

// ---------------- scratch (device globals: allocation-free) ----------------
__device__ __align__(16) __nv_bfloat16 g_Ahi[Mq * Dq];
__device__ __align__(16) __nv_bfloat16 g_Alo[Mq * Dq];
__device__ __align__(16) __nv_bfloat16 g_Whi[4][Dq * Dq];   // transposed: [n][k]
__device__ __align__(16) __nv_bfloat16 g_Wlo[4][Dq * Dq];
__device__ __align__(16) __nv_bfloat16 g_Qh[Mq * Dq];
__device__ __align__(16) __nv_bfloat16 g_Ql[Mq * Dq];
__device__ __align__(16) __nv_bfloat16 g_Kh[Mq * Dq];
__device__ __align__(16) __nv_bfloat16 g_Kl[Mq * Dq];
__device__ __align__(16) __nv_bfloat16 g_Vh[Mq * Dq];
__device__ __align__(16) __nv_bfloat16 g_Vl[Mq * Dq];
__device__ __align__(16) __nv_bfloat16 g_AOh[Mq * Dq];
__device__ __align__(16) __nv_bfloat16 g_AOl[Mq * Dq];

// ---------------------------------------------------------------------------
__device__ __forceinline__ uint32_t smem_u32(const void* p) {
    uint32_t a;
    asm("{ .reg .u64 t; cvta.to.shared.u64 t, %1; cvt.u32.u64 %0, t; }" : "=r"(a) : "l"(p));
    return a;
}
__device__ __forceinline__ void cp_async16(uint32_t saddr, const void* gaddr) {
    asm volatile("cp.async.cg.shared.global [%0], [%1], 16;" :: "r"(saddr), "l"(gaddr));
}
__device__ __forceinline__ void ldsm_x4(uint32_t* r, uint32_t saddr) {
    asm volatile("ldmatrix.sync.aligned.m8n8.x4.shared.b16 {%0,%1,%2,%3}, [%4];"
                 : "=r"(r[0]), "=r"(r[1]), "=r"(r[2]), "=r"(r[3]) : "r"(saddr));
}
__device__ __forceinline__ void ldsm_x4_t(uint32_t* r, uint32_t saddr) {
    asm volatile("ldmatrix.sync.aligned.m8n8.x4.trans.shared.b16 {%0,%1,%2,%3}, [%4];"
                 : "=r"(r[0]), "=r"(r[1]), "=r"(r[2]), "=r"(r[3]) : "r"(saddr));
}
__device__ __forceinline__ void mma16816(float* d, const uint32_t* a, uint32_t b0, uint32_t b1) {
    asm volatile(
        "mma.sync.aligned.m16n8k16.row.col.f32.bf16.bf16.f32 "
        "{%0,%1,%2,%3}, {%4,%5,%6,%7}, {%8,%9}, {%0,%1,%2,%3};"
        : "+f"(d[0]), "+f"(d[1]), "+f"(d[2]), "+f"(d[3])
        : "r"(a[0]), "r"(a[1]), "r"(a[2]), "r"(a[3]), "r"(b0), "r"(b1));
}

// ---------------------------------------------------------------------------
// fp32 -> bf16 hi/lo split (elementwise)  -- for x only
// ---------------------------------------------------------------------------
__global__ void split_kernel(const float* __restrict__ src,
                             __nv_bfloat16* __restrict__ hi,
                             __nv_bfloat16* __restrict__ lo, int n)
{
    int i = (blockIdx.x * blockDim.x + threadIdx.x) * 4;
    if (i >= n) return;
    float4 v = *(const float4*)(src + i);
    __nv_bfloat16 h0 = __float2bfloat16(v.x), h1 = __float2bfloat16(v.y);
    __nv_bfloat16 h2 = __float2bfloat16(v.z), h3 = __float2bfloat16(v.w);
    __nv_bfloat16 l0 = __float2bfloat16(v.x - __bfloat162float(h0));
    __nv_bfloat16 l1 = __float2bfloat16(v.y - __bfloat162float(h1));
    __nv_bfloat16 l2 = __float2bfloat16(v.z - __bfloat162float(h2));
    __nv_bfloat16 l3 = __float2bfloat16(v.w - __bfloat162float(h3));
    ((__nv_bfloat162*)(hi + i))[0] = __halves2bfloat162(h0, h1);
    ((__nv_bfloat162*)(hi + i))[1] = __halves2bfloat162(h2, h3);
    ((__nv_bfloat162*)(lo + i))[0] = __halves2bfloat162(l0, l1);
    ((__nv_bfloat162*)(lo + i))[1] = __halves2bfloat162(l2, l3);
}

// ---------------------------------------------------------------------------
// W[k][n] fp32 -> Wt_hi/lo[n][k] bf16 (transposed split)
// ---------------------------------------------------------------------------
__global__ void transpose_split_kernel(const float* __restrict__ W,
                                       __nv_bfloat16* __restrict__ hi,
                                       __nv_bfloat16* __restrict__ lo)
{
    __shared__ float tile[32][33];
    int n0 = blockIdx.x * 32, k0 = blockIdx.y * 32;
    int x = threadIdx.x, y = threadIdx.y;  // 32 x 8
#pragma unroll
    for (int r = 0; r < 32; r += 8)
        tile[y + r][x] = W[(size_t)(k0 + y + r) * Dq + n0 + x];
    __syncthreads();
#pragma unroll
    for (int r = 0; r < 32; r += 8) {
        float v = tile[x][y + r];
        __nv_bfloat16 h = __float2bfloat16(v);
        hi[(size_t)(n0 + y + r) * Dq + k0 + x] = h;
        lo[(size_t)(n0 + y + r) * Dq + k0 + x] = __float2bfloat16(v - __bfloat162float(h));
    }
}

// ---------------------------------------------------------------------------
// mma.sync GEMM: 3-pass bf16 split. Block 128x128, 8 warps, BK=32, 3-stage.
// MODE 0: C = fp32 out (+bias).  MODE 1: write hi/lo bf16 of (C+bias)*scale.
// ---------------------------------------------------------------------------
#define GSTAGE 20480
#define GEMM_SMEM (3 * GSTAGE)

template<int MODE>
__global__ void __launch_bounds__(256, 2)
gemm_mma(const __nv_bfloat16* __restrict__ Ah, const __nv_bfloat16* __restrict__ Al,
         const __nv_bfloat16* __restrict__ Bh, const __nv_bfloat16* __restrict__ Bl,
         const float* __restrict__ bias, float scale,
         float* __restrict__ Cf,
         __nv_bfloat16* __restrict__ Chi, __nv_bfloat16* __restrict__ Clo)
{
    extern __shared__ char smc[];
    const uint32_t smb = smem_u32(smc);
    const int t = threadIdx.x, lane = t & 31, wid = t >> 5;
    const int wm = wid >> 2, wn = wid & 3;
    const int m0 = blockIdx.y * 128, n0 = blockIdx.x * 128;

    float acc[4][4][4];
#pragma unroll
    for (int i = 0; i < 4; i++)
#pragma unroll
        for (int j = 0; j < 4; j++)
#pragma unroll
            for (int k = 0; k < 4; k++) acc[i][j][k] = 0.f;

    const __nv_bfloat16* Asrc[3] = { Ah + (size_t)m0 * Dq, Ah + (size_t)m0 * Dq,
                                     Al + (size_t)m0 * Dq };
    const __nv_bfloat16* Bsrc[3] = { Bh + (size_t)n0 * Dq, Bl + (size_t)n0 * Dq,
                                     Bh + (size_t)n0 * Dq };

    const int r0c = t >> 1, s0c = (t & 1) * 2;

    auto issue = [&](int c) {
        const int st = c % 3, pass = c >> 5, kk = (c & 31) * 32;
        const uint32_t abase = smb + st * GSTAGE;
        const uint32_t bbase = abase + 10240;
        const __nv_bfloat16* As = Asrc[pass] + kk;
        const __nv_bfloat16* Bs = Bsrc[pass] + kk;
#pragma unroll
        for (int it = 0; it < 2; ++it) {
            int seg = s0c + it;
            cp_async16(abase + r0c * 80 + seg * 16, As + (size_t)r0c * Dq + seg * 8);
            cp_async16(bbase + r0c * 80 + seg * 16, Bs + (size_t)r0c * Dq + seg * 8);
        }
        asm volatile("cp.async.commit_group;" ::: "memory");
    };

    issue(0);
    issue(1);

    for (int c = 0; c < 96; ++c) {
        if (c < 94) asm volatile("cp.async.wait_group 1;" ::: "memory");
        else        asm volatile("cp.async.wait_group 0;" ::: "memory");
        __syncthreads();

        if (c + 2 < 96) issue(c + 2);

        const int st = c % 3;
        const uint32_t abase = smb + st * GSTAGE;
        const uint32_t bbase = abase + 10240;

#pragma unroll
        for (int ks = 0; ks < 2; ++ks) {
            uint32_t a[4][4], b[2][4];
#pragma unroll
            for (int mi = 0; mi < 4; ++mi) {
                int row  = wm * 64 + mi * 16 + (lane & 15);
                int colh = ks * 16 + (lane >> 4) * 8;
                ldsm_x4(a[mi], abase + row * 80 + colh * 2);
            }
#pragma unroll
            for (int g = 0; g < 2; ++g) {
                int row  = wn * 32 + g * 16 + ((lane >> 4) & 1) * 8 + (lane & 7);
                int colh = ks * 16 + ((lane >> 3) & 1) * 8;
                ldsm_x4(b[g], bbase + row * 80 + colh * 2);
            }
#pragma unroll
            for (int mi = 0; mi < 4; ++mi)
#pragma unroll
                for (int ni = 0; ni < 4; ++ni)
                    mma16816(acc[mi][ni], a[mi],
                             b[ni >> 1][(ni & 1) * 2], b[ni >> 1][(ni & 1) * 2 + 1]);
        }
    }

#pragma unroll
    for (int mi = 0; mi < 4; ++mi) {
#pragma unroll
        for (int ni = 0; ni < 4; ++ni) {
            int row = m0 + wm * 64 + mi * 16 + (lane >> 2);
            int col = n0 + wn * 32 + ni * 8 + (lane & 3) * 2;
            float b0 = bias[col], b1 = bias[col + 1];
            if (MODE == 0) {
                float2 v0 = { acc[mi][ni][0] + b0, acc[mi][ni][1] + b1 };
                float2 v1 = { acc[mi][ni][2] + b0, acc[mi][ni][3] + b1 };
                *(float2*)(Cf + (size_t)row * Dq + col)       = v0;
                *(float2*)(Cf + (size_t)(row + 8) * Dq + col) = v1;
            } else {
                float v0 = (acc[mi][ni][0] + b0) * scale;
                float v1 = (acc[mi][ni][1] + b1) * scale;
                float v2 = (acc[mi][ni][2] + b0) * scale;
                float v3 = (acc[mi][ni][3] + b1) * scale;
                __nv_bfloat16 h0 = __float2bfloat16(v0), h1 = __float2bfloat16(v1);
                __nv_bfloat16 h2 = __float2bfloat16(v2), h3 = __float2bfloat16(v3);
                __nv_bfloat16 e0 = __float2bfloat16(v0 - __bfloat162float(h0));
                __nv_bfloat16 e1 = __float2bfloat16(v1 - __bfloat162float(h1));
                __nv_bfloat16 e2 = __float2bfloat16(v2 - __bfloat162float(h2));
                __nv_bfloat16 e3 = __float2bfloat16(v3 - __bfloat162float(h3));
                *(__nv_bfloat162*)(Chi + (size_t)row * Dq + col)       = __halves2bfloat162(h0, h1);
                *(__nv_bfloat162*)(Chi + (size_t)(row + 8) * Dq + col) = __halves2bfloat162(h2, h3);
                *(__nv_bfloat162*)(Clo + (size_t)row * Dq + col)       = __halves2bfloat162(e0, e1);
                *(__nv_bfloat162*)(Clo + (size_t)(row + 8) * Dq + col) = __halves2bfloat162(e2, e3);
            }
        }
    }
}

// ---------------------------------------------------------------------------
// Tensor-core flash attention (causal).
// CTA: 128 q rows x one (b,h). 8 warps, each owns 16 q rows x 64-key tiles.
// QK^T and P@V on mma.sync bf16 with hi/lo split (3 passes each).
// smem: Qh (persistent) 18KB | P hi/lo 36KB (Ql staged here first) | K/V 36KB.
// ---------------------------------------------------------------------------
#define ATT_SMEM 92160

__global__ void __launch_bounds__(256, 2)
attn_mma(const __nv_bfloat16* __restrict__ Qh_g, const __nv_bfloat16* __restrict__ Ql_g,
         const __nv_bfloat16* __restrict__ Kh_g, const __nv_bfloat16* __restrict__ Kl_g,
         const __nv_bfloat16* __restrict__ Vh_g, const __nv_bfloat16* __restrict__ Vl_g,
         __nv_bfloat16* __restrict__ AOh_g, __nv_bfloat16* __restrict__ AOl_g)
{
    extern __shared__ char smc[];
    const uint32_t smb = smem_u32(smc);
    const int t = threadIdx.x, lane = t & 31, w = t >> 5;
    const int qt = blockIdx.x;
    const int b = blockIdx.y >> 4, h = blockIdx.y & 15;
    const size_t row0 = (size_t)b * Tq + qt * 128;

    const uint32_t SQH = smb;            // Qh: 128 x 144B
    const uint32_t SPH = smb + 18432;    // P hi (Ql staging first)
    const uint32_t SPL = smb + 36864;    // P lo
    const uint32_t SKH = smb + 55296;    // K hi: 64 x 144B
    const uint32_t SKL = smb + 64512;
    const uint32_t SVH = smb + 73728;
    const uint32_t SVL = smb + 82944;

    // ---- prologue: stage Qh -> SQH, Ql -> SPH; cache Ql frags in regs
#pragma unroll
    for (int i = 0; i < 4; ++i) {
        int idx = t + i * 256, r = idx >> 3, s = idx & 7;
        size_t g = (row0 + r) * Dq + h * 64 + s * 8;
        cp_async16(SQH + r * 144 + s * 16, Qh_g + g);
        cp_async16(SPH + r * 144 + s * 16, Ql_g + g);
    }
    asm volatile("cp.async.commit_group;" ::: "memory");
    asm volatile("cp.async.wait_group 0;" ::: "memory");
    __syncthreads();

    const uint32_t arow = w * 16 + (lane & 15);
    const uint32_t aco  = (lane >> 4) * 8;
    uint32_t ql[4][4];
#pragma unroll
    for (int ks = 0; ks < 4; ++ks)
        ldsm_x4(ql[ks], SPH + arow * 144 + (ks * 16 + aco) * 2);
    __syncthreads();   // Ql staging consumed; SPH/SPL free for P

    float m0 = -1e30f, m1 = -1e30f, l0 = 0.f, l1 = 0.f;
    float oac[8][4];
#pragma unroll
    for (int ng = 0; ng < 8; ++ng)
#pragma unroll
        for (int k = 0; k < 4; ++k) oac[ng][k] = 0.f;

    const uint32_t krow = ((lane >> 4) & 1) * 8 + (lane & 7);
    const uint32_t kco  = ((lane >> 3) & 1) * 8;
    const uint32_t vrow = ((lane >> 3) & 1) * 8 + (lane & 7);
    const uint32_t vco  = ((lane >> 4) & 1) * 8;

    const int jtmax = 2 * qt + 1;
    for (int jt = 0; jt <= jtmax; ++jt) {
        // load K/V hi/lo tiles (64 x 64 each)
#pragma unroll
        for (int i = 0; i < 8; ++i) {
            int idx = t + i * 256;
            int mat = idx >> 9, rem = idx & 511, r = rem >> 3, s = rem & 7;
            const __nv_bfloat16* src = (mat == 0) ? Kh_g : (mat == 1) ? Kl_g
                                     : (mat == 2) ? Vh_g : Vl_g;
            size_t g = ((size_t)b * Tq + jt * 64 + r) * Dq + h * 64 + s * 8;
            cp_async16(SKH + mat * 9216 + r * 144 + s * 16, src + g);
        }
        asm volatile("cp.async.commit_group;" ::: "memory");
        asm volatile("cp.async.wait_group 0;" ::: "memory");
        __syncthreads();

        // ---- S = Qs @ K^T (3-pass split)
        float sac[8][4];
#pragma unroll
        for (int ng = 0; ng < 8; ++ng)
#pragma unroll
            for (int k = 0; k < 4; ++k) sac[ng][k] = 0.f;

#pragma unroll
        for (int ks = 0; ks < 4; ++ks) {
            uint32_t qh[4];
            ldsm_x4(qh, SQH + arow * 144 + (ks * 16 + aco) * 2);
            uint32_t kb[4][4];
#pragma unroll
            for (int g = 0; g < 4; ++g)
                ldsm_x4(kb[g], SKH + (g * 16 + krow) * 144 + (ks * 16 + kco) * 2);
#pragma unroll
            for (int g = 0; g < 4; ++g) {
                mma16816(sac[2*g],   qh,     kb[g][0], kb[g][1]);
                mma16816(sac[2*g+1], qh,     kb[g][2], kb[g][3]);
                mma16816(sac[2*g],   ql[ks], kb[g][0], kb[g][1]);
                mma16816(sac[2*g+1], ql[ks], kb[g][2], kb[g][3]);
            }
#pragma unroll
            for (int g = 0; g < 4; ++g)
                ldsm_x4(kb[g], SKL + (g * 16 + krow) * 144 + (ks * 16 + kco) * 2);
#pragma unroll
            for (int g = 0; g < 4; ++g) {
                mma16816(sac[2*g],   qh, kb[g][0], kb[g][1]);
                mma16816(sac[2*g+1], qh, kb[g][2], kb[g][3]);
            }
        }

        // ---- causal mask (only possibly-diagonal tiles)
        if (jt >= 2 * qt) {
            int q0 = qt * 128 + w * 16 + (lane >> 2);
#pragma unroll
            for (int ng = 0; ng < 8; ++ng) {
                int k0 = jt * 64 + ng * 8 + (lane & 3) * 2;
                if (k0     > q0)     sac[ng][0] = -1e30f;
                if (k0 + 1 > q0)     sac[ng][1] = -1e30f;
                if (k0     > q0 + 8) sac[ng][2] = -1e30f;
                if (k0 + 1 > q0 + 8) sac[ng][3] = -1e30f;
            }
        }

        // ---- online softmax (rows r and r+8; quad lanes share a row)
        float mx0 = -1e30f, mx1 = -1e30f;
#pragma unroll
        for (int ng = 0; ng < 8; ++ng) {
            mx0 = fmaxf(mx0, fmaxf(sac[ng][0], sac[ng][1]));
            mx1 = fmaxf(mx1, fmaxf(sac[ng][2], sac[ng][3]));
        }
        mx0 = fmaxf(mx0, __shfl_xor_sync(0xffffffffu, mx0, 1));
        mx0 = fmaxf(mx0, __shfl_xor_sync(0xffffffffu, mx0, 2));
        mx1 = fmaxf(mx1, __shfl_xor_sync(0xffffffffu, mx1, 1));
        mx1 = fmaxf(mx1, __shfl_xor_sync(0xffffffffu, mx1, 2));
        float mn0 = fmaxf(m0, mx0), mn1 = fmaxf(m1, mx1);
        float a0 = __expf(m0 - mn0), a1 = __expf(m1 - mn1);
        m0 = mn0; m1 = mn1;

        float rs0 = 0.f, rs1 = 0.f;
        const uint32_t poff0 = (w * 16 + (lane >> 2)) * 144 + ((lane & 3) * 2) * 2;
#pragma unroll
        for (int ng = 0; ng < 8; ++ng) {
            float p0 = __expf(sac[ng][0] - mn0), p1 = __expf(sac[ng][1] - mn0);
            float p2 = __expf(sac[ng][2] - mn1), p3 = __expf(sac[ng][3] - mn1);
            rs0 += p0 + p1; rs1 += p2 + p3;
            __nv_bfloat16 h0 = __float2bfloat16(p0), h1 = __float2bfloat16(p1);
            __nv_bfloat16 h2 = __float2bfloat16(p2), h3 = __float2bfloat16(p3);
            __nv_bfloat16 e0 = __float2bfloat16(p0 - __bfloat162float(h0));
            __nv_bfloat16 e1 = __float2bfloat16(p1 - __bfloat162float(h1));
            __nv_bfloat16 e2 = __float2bfloat16(p2 - __bfloat162float(h2));
            __nv_bfloat16 e3 = __float2bfloat16(p3 - __bfloat162float(h3));
            uint32_t o0 = poff0 + ng * 16;
            *(__nv_bfloat162*)(smc + 18432 + o0)           = __halves2bfloat162(h0, h1);
            *(__nv_bfloat162*)(smc + 18432 + o0 + 8 * 144) = __halves2bfloat162(h2, h3);
            *(__nv_bfloat162*)(smc + 36864 + o0)           = __halves2bfloat162(e0, e1);
            *(__nv_bfloat162*)(smc + 36864 + o0 + 8 * 144) = __halves2bfloat162(e2, e3);
        }
        rs0 += __shfl_xor_sync(0xffffffffu, rs0, 1);
        rs0 += __shfl_xor_sync(0xffffffffu, rs0, 2);
        rs1 += __shfl_xor_sync(0xffffffffu, rs1, 1);
        rs1 += __shfl_xor_sync(0xffffffffu, rs1, 2);
        l0 = l0 * a0 + rs0; l1 = l1 * a1 + rs1;
#pragma unroll
        for (int ng = 0; ng < 8; ++ng) {
            oac[ng][0] *= a0; oac[ng][1] *= a0;
            oac[ng][2] *= a1; oac[ng][3] *= a1;
        }
        __syncwarp();   // P visible within warp (A-frag rows are warp-local)

        // ---- O += P @ V (3-pass split; V via ldmatrix.trans)
#pragma unroll
        for (int ks = 0; ks < 4; ++ks) {
            uint32_t ph[4], pl[4];
            ldsm_x4(ph, SPH + arow * 144 + (ks * 16 + aco) * 2);
            ldsm_x4(pl, SPL + arow * 144 + (ks * 16 + aco) * 2);
#pragma unroll
            for (int g = 0; g < 4; ++g) {
                uint32_t vb[4];
                ldsm_x4_t(vb, SVH + (ks * 16 + vrow) * 144 + (g * 16 + vco) * 2);
                mma16816(oac[2*g],   ph, vb[0], vb[1]);
                mma16816(oac[2*g+1], ph, vb[2], vb[3]);
                mma16816(oac[2*g],   pl, vb[0], vb[1]);
                mma16816(oac[2*g+1], pl, vb[2], vb[3]);
                ldsm_x4_t(vb, SVL + (ks * 16 + vrow) * 144 + (g * 16 + vco) * 2);
                mma16816(oac[2*g],   ph, vb[0], vb[1]);
                mma16816(oac[2*g+1], ph, vb[2], vb[3]);
            }
        }
        __syncthreads();   // K/V reads done before next tile's cp.async
    }

    // ---- epilogue: normalize, split to bf16 hi/lo, store AO
    float i0 = 1.f / l0, i1 = 1.f / l1;
    size_t gr0 = row0 + w * 16 + (lane >> 2);
#pragma unroll
    for (int ng = 0; ng < 8; ++ng) {
        int col = h * 64 + ng * 8 + (lane & 3) * 2;
        float v0 = oac[ng][0] * i0, v1 = oac[ng][1] * i0;
        float v2 = oac[ng][2] * i1, v3 = oac[ng][3] * i1;
        __nv_bfloat16 h0 = __float2bfloat16(v0), h1 = __float2bfloat16(v1);
        __nv_bfloat16 h2 = __float2bfloat16(v2), h3 = __float2bfloat16(v3);
        __nv_bfloat16 e0 = __float2bfloat16(v0 - __bfloat162float(h0));
        __nv_bfloat16 e1 = __float2bfloat16(v1 - __bfloat162float(h1));
        __nv_bfloat16 e2 = __float2bfloat16(v2 - __bfloat162float(h2));
        __nv_bfloat16 e3 = __float2bfloat16(v3 - __bfloat162float(h3));
        *(__nv_bfloat162*)(AOh_g + gr0 * Dq + col)       = __halves2bfloat162(h0, h1);
        *(__nv_bfloat162*)(AOh_g + (gr0 + 8) * Dq + col) = __halves2bfloat162(h2, h3);
        *(__nv_bfloat162*)(AOl_g + gr0 * Dq + col)       = __halves2bfloat162(e0, e1);
        *(__nv_bfloat162*)(AOl_g + (gr0 + 8) * Dq + col) = __halves2bfloat162(e2, e3);
    }
}

// ---------------------------------------------------------------------------
extern "C" void kernel_launch(void* const* d_in, const int* in_sizes, int n_in,
                              void* d_out, int out_size)
{
    const float* x  = (const float*)d_in[0];
    const float* Wq = (const float*)d_in[2];
    const float* bq = (const float*)d_in[3];
    const float* Wk = (const float*)d_in[4];
    const float* bk = (const float*)d_in[5];
    const float* Wv = (const float*)d_in[6];
    const float* bv = (const float*)d_in[7];
    const float* Wo = (const float*)d_in[8];
    const float* bo = (const float*)d_in[9];
    float* out = (float*)d_out;

    __nv_bfloat16 *ahi, *alo, *whi, *wlo;
    __nv_bfloat16 *qh, *qlp, *kh, *kl, *vh, *vl, *aoh, *aol;
    cudaGetSymbolAddress((void**)&ahi, g_Ahi);
    cudaGetSymbolAddress((void**)&alo, g_Alo);
    cudaGetSymbolAddress((void**)&whi, g_Whi);
    cudaGetSymbolAddress((void**)&wlo, g_Wlo);
    cudaGetSymbolAddress((void**)&qh,  g_Qh);
    cudaGetSymbolAddress((void**)&qlp, g_Ql);
    cudaGetSymbolAddress((void**)&kh,  g_Kh);
    cudaGetSymbolAddress((void**)&kl,  g_Kl);
    cudaGetSymbolAddress((void**)&vh,  g_Vh);
    cudaGetSymbolAddress((void**)&vl,  g_Vl);
    cudaGetSymbolAddress((void**)&aoh, g_AOh);
    cudaGetSymbolAddress((void**)&aol, g_AOl);

    cudaFuncSetAttribute(gemm_mma<0>, cudaFuncAttributeMaxDynamicSharedMemorySize, GEMM_SMEM);
    cudaFuncSetAttribute(gemm_mma<1>, cudaFuncAttributeMaxDynamicSharedMemorySize, GEMM_SMEM);
    cudaFuncSetAttribute(attn_mma, cudaFuncAttributeMaxDynamicSharedMemorySize, ATT_SMEM);

    const int NPROJ = Mq * Dq;
    dim3 tsg(32, 32), tsb(32, 8);
    dim3 ggrid(Dq / 128, Mq / 128);      // (8, 32)

    split_kernel<<<NPROJ / 1024, 256>>>(x, ahi, alo, NPROJ);
    const float* Ws[4] = { Wq, Wk, Wv, Wo };
    for (int w = 0; w < 4; ++w)
        transpose_split_kernel<<<tsg, tsb>>>(Ws[w], whi + (size_t)w * Dq * Dq,
                                             wlo + (size_t)w * Dq * Dq);

    // Q/K/V projections -> bf16 hi/lo (Q pre-scaled by 1/sqrt(64))
    gemm_mma<1><<<ggrid, 256, GEMM_SMEM>>>(ahi, alo, whi, wlo, bq, 0.125f,
                                           nullptr, qh, qlp);
    gemm_mma<1><<<ggrid, 256, GEMM_SMEM>>>(ahi, alo, whi + (size_t)Dq * Dq,
                                           wlo + (size_t)Dq * Dq, bk, 1.f,
                                           nullptr, kh, kl);
    gemm_mma<1><<<ggrid, 256, GEMM_SMEM>>>(ahi, alo, whi + 2 * (size_t)Dq * Dq,
                                           wlo + 2 * (size_t)Dq * Dq, bv, 1.f,
                                           nullptr, vh, vl);

    dim3 agrid(Tq / 128, Bq * Hq);       // (16, 32)
    attn_mma<<<agrid, 256, ATT_SMEM>>>(qh, qlp, kh, kl, vh, vl, aoh, aol);

    gemm_mma<0><<<ggrid, 256, GEMM_SMEM>>>(aoh, aol, whi + 3 * (size_t)Dq * Dq,
                                           wlo + 3 * (size_t)Dq * Dq, bo, 1.f,
                                           out, nullptr, nullptr);
}

// round 5
// speedup vs baseline: 2.5327x; 1.1685x over previous
#include <cuda_runtime.h>
#include <cuda_bf16.h>
#include <cstdint>
#include <cstddef>

#define Bq   2
#define Tq   2048
#define Dq   1024
#define Hq   16
#define DKq  64
#define Mq   (Bq*Tq)     // 4096

// ---------------- scratch (device globals: allocation-free) ----------------
__device__ __align__(16) __nv_bfloat16 g_Ahi[Mq * Dq];
__device__ __align__(16) __nv_bfloat16 g_Alo[Mq * Dq];
__device__ __align__(16) __nv_bfloat16 g_Whi[4][Dq * Dq];   // transposed [n][k]
__device__ __align__(16) __nv_bfloat16 g_Wlo[4][Dq * Dq];
__device__ __align__(16) __nv_bfloat16 g_Qh[Mq * Dq];
__device__ __align__(16) __nv_bfloat16 g_Ql[Mq * Dq];
__device__ __align__(16) __nv_bfloat16 g_Kh[Mq * Dq];
__device__ __align__(16) __nv_bfloat16 g_Kl[Mq * Dq];
__device__ __align__(16) __nv_bfloat16 g_Vh[Mq * Dq];
__device__ __align__(16) __nv_bfloat16 g_Vl[Mq * Dq];
__device__ __align__(16) __nv_bfloat16 g_AOh[Mq * Dq];
__device__ __align__(16) __nv_bfloat16 g_AOl[Mq * Dq];

// ---------------------------------------------------------------------------
__device__ __forceinline__ uint32_t smem_u32(const void* p) {
    uint32_t a;
    asm("{ .reg .u64 t; cvta.to.shared.u64 t, %1; cvt.u32.u64 %0, t; }" : "=r"(a) : "l"(p));
    return a;
}
__device__ __forceinline__ void cp_async16(uint32_t saddr, const void* gaddr) {
    asm volatile("cp.async.cg.shared.global [%0], [%1], 16;" :: "r"(saddr), "l"(gaddr));
}
__device__ __forceinline__ void ldsm_x4(uint32_t* r, uint32_t saddr) {
    asm volatile("ldmatrix.sync.aligned.m8n8.x4.shared.b16 {%0,%1,%2,%3}, [%4];"
                 : "=r"(r[0]), "=r"(r[1]), "=r"(r[2]), "=r"(r[3]) : "r"(saddr));
}
__device__ __forceinline__ void ldsm_x4_t(uint32_t* r, uint32_t saddr) {
    asm volatile("ldmatrix.sync.aligned.m8n8.x4.trans.shared.b16 {%0,%1,%2,%3}, [%4];"
                 : "=r"(r[0]), "=r"(r[1]), "=r"(r[2]), "=r"(r[3]) : "r"(saddr));
}
__device__ __forceinline__ void mma16816(float* d, const uint32_t* a, uint32_t b0, uint32_t b1) {
    asm volatile(
        "mma.sync.aligned.m16n8k16.row.col.f32.bf16.bf16.f32 "
        "{%0,%1,%2,%3}, {%4,%5,%6,%7}, {%8,%9}, {%0,%1,%2,%3};"
        : "+f"(d[0]), "+f"(d[1]), "+f"(d[2]), "+f"(d[3])
        : "r"(a[0]), "r"(a[1]), "r"(a[2]), "r"(a[3]), "r"(b0), "r"(b1));
}
__device__ __forceinline__ uint32_t pack_bf16x2(float a, float b) {
    __nv_bfloat162 t = __halves2bfloat162(__float2bfloat16(a), __float2bfloat16(b));
    return *(uint32_t*)&t;
}

// ---------------------------------------------------------------------------
__global__ void split_kernel(const float* __restrict__ src,
                             __nv_bfloat16* __restrict__ hi,
                             __nv_bfloat16* __restrict__ lo, int n)
{
    int i = (blockIdx.x * blockDim.x + threadIdx.x) * 4;
    if (i >= n) return;
    float4 v = *(const float4*)(src + i);
    __nv_bfloat16 h0 = __float2bfloat16(v.x), h1 = __float2bfloat16(v.y);
    __nv_bfloat16 h2 = __float2bfloat16(v.z), h3 = __float2bfloat16(v.w);
    __nv_bfloat16 l0 = __float2bfloat16(v.x - __bfloat162float(h0));
    __nv_bfloat16 l1 = __float2bfloat16(v.y - __bfloat162float(h1));
    __nv_bfloat16 l2 = __float2bfloat16(v.z - __bfloat162float(h2));
    __nv_bfloat16 l3 = __float2bfloat16(v.w - __bfloat162float(h3));
    ((__nv_bfloat162*)(hi + i))[0] = __halves2bfloat162(h0, h1);
    ((__nv_bfloat162*)(hi + i))[1] = __halves2bfloat162(h2, h3);
    ((__nv_bfloat162*)(lo + i))[0] = __halves2bfloat162(l0, l1);
    ((__nv_bfloat162*)(lo + i))[1] = __halves2bfloat162(l2, l3);
}

__global__ void transpose_split_kernel(const float* __restrict__ W,
                                       __nv_bfloat16* __restrict__ hi,
                                       __nv_bfloat16* __restrict__ lo)
{
    __shared__ float tile[32][33];
    int n0 = blockIdx.x * 32, k0 = blockIdx.y * 32;
    int x = threadIdx.x, y = threadIdx.y;
#pragma unroll
    for (int r = 0; r < 32; r += 8)
        tile[y + r][x] = W[(size_t)(k0 + y + r) * Dq + n0 + x];
    __syncthreads();
#pragma unroll
    for (int r = 0; r < 32; r += 8) {
        float v = tile[x][y + r];
        __nv_bfloat16 h = __float2bfloat16(v);
        hi[(size_t)(n0 + y + r) * Dq + k0 + x] = h;
        lo[(size_t)(n0 + y + r) * Dq + k0 + x] = __float2bfloat16(v - __bfloat162float(h));
    }
}

// ---------------------------------------------------------------------------
// Fused-split GEMM: C = Ah*Bh + Ah*Bl + Al*Bh (+bias).
// Block 128x128, 8 warps (64x32 warp tile), BK=32, 2-stage cp.async.
// Stage: Ah|Al|Bh|Bl, each 128 x 80B = 10240B -> 40960B/stage.
// ---------------------------------------------------------------------------
#define GSTAGE 40960
#define GEMM_SMEM (2 * GSTAGE)

template<int MODE>
__global__ void __launch_bounds__(256, 2)
gemm_mma(const __nv_bfloat16* __restrict__ Ah, const __nv_bfloat16* __restrict__ Al,
         const __nv_bfloat16* __restrict__ Bh, const __nv_bfloat16* __restrict__ Bl,
         const float* __restrict__ bias, float scale,
         float* __restrict__ Cf,
         __nv_bfloat16* __restrict__ Chi, __nv_bfloat16* __restrict__ Clo)
{
    extern __shared__ char smc[];
    const uint32_t smb = smem_u32(smc);
    const int t = threadIdx.x, lane = t & 31, wid = t >> 5;
    const int wm = wid >> 2, wn = wid & 3;
    const int m0 = blockIdx.y * 128, n0 = blockIdx.x * 128;

    float acc[4][4][4];
#pragma unroll
    for (int i = 0; i < 4; i++)
#pragma unroll
        for (int j = 0; j < 4; j++)
#pragma unroll
            for (int k = 0; k < 4; k++) acc[i][j][k] = 0.f;

    const __nv_bfloat16* mats[4] = { Ah + (size_t)m0 * Dq, Al + (size_t)m0 * Dq,
                                     Bh + (size_t)n0 * Dq, Bl + (size_t)n0 * Dq };
    const int r0c = t >> 1, s0c = (t & 1) * 2;

    auto issue = [&](int c) {
        const uint32_t base = smb + (uint32_t)(c & 1) * GSTAGE;
        const int kk = c * 32;
#pragma unroll
        for (int mat = 0; mat < 4; ++mat) {
            const __nv_bfloat16* s = mats[mat] + kk;
#pragma unroll
            for (int it = 0; it < 2; ++it) {
                int seg = s0c + it;
                cp_async16(base + mat * 10240 + r0c * 80 + seg * 16,
                           s + (size_t)r0c * Dq + seg * 8);
            }
        }
        asm volatile("cp.async.commit_group;" ::: "memory");
    };

    issue(0);

    const int arow = wm * 64 + (lane & 15);
    const int aco  = (lane >> 4) * 8;
    const int brow0 = wn * 32 + ((lane >> 4) & 1) * 8 + (lane & 7);
    const int bco  = ((lane >> 3) & 1) * 8;

    for (int c = 0; c < 32; ++c) {
        if (c + 1 < 32) issue(c + 1);
        if (c + 1 < 32) asm volatile("cp.async.wait_group 1;" ::: "memory");
        else            asm volatile("cp.async.wait_group 0;" ::: "memory");
        __syncthreads();

        const uint32_t bAh = smb + (uint32_t)(c & 1) * GSTAGE;
        const uint32_t bAl = bAh + 10240, bBh = bAh + 20480, bBl = bAh + 30720;

#pragma unroll
        for (int ks = 0; ks < 2; ++ks) {
            const int kof = (ks * 16 + aco) * 2;
            const int kofb = (ks * 16 + bco) * 2;
            uint32_t ah[4][4], bb[2][4];
#pragma unroll
            for (int mi = 0; mi < 4; ++mi)
                ldsm_x4(ah[mi], bAh + (arow + mi * 16) * 80 + kof);
#pragma unroll
            for (int g = 0; g < 2; ++g)
                ldsm_x4(bb[g], bBh + (brow0 + g * 16) * 80 + kofb);
            // hh
#pragma unroll
            for (int mi = 0; mi < 4; ++mi)
#pragma unroll
                for (int ni = 0; ni < 4; ++ni)
                    mma16816(acc[mi][ni], ah[mi],
                             bb[ni >> 1][(ni & 1) * 2], bb[ni >> 1][(ni & 1) * 2 + 1]);
            // hl
            uint32_t bl[2][4];
#pragma unroll
            for (int g = 0; g < 2; ++g)
                ldsm_x4(bl[g], bBl + (brow0 + g * 16) * 80 + kofb);
#pragma unroll
            for (int mi = 0; mi < 4; ++mi)
#pragma unroll
                for (int ni = 0; ni < 4; ++ni)
                    mma16816(acc[mi][ni], ah[mi],
                             bl[ni >> 1][(ni & 1) * 2], bl[ni >> 1][(ni & 1) * 2 + 1]);
            // lh
            uint32_t al[4][4];
#pragma unroll
            for (int mi = 0; mi < 4; ++mi)
                ldsm_x4(al[mi], bAl + (arow + mi * 16) * 80 + kof);
#pragma unroll
            for (int mi = 0; mi < 4; ++mi)
#pragma unroll
                for (int ni = 0; ni < 4; ++ni)
                    mma16816(acc[mi][ni], al[mi],
                             bb[ni >> 1][(ni & 1) * 2], bb[ni >> 1][(ni & 1) * 2 + 1]);
        }
        __syncthreads();
    }

#pragma unroll
    for (int mi = 0; mi < 4; ++mi) {
#pragma unroll
        for (int ni = 0; ni < 4; ++ni) {
            int row = m0 + wm * 64 + mi * 16 + (lane >> 2);
            int col = n0 + wn * 32 + ni * 8 + (lane & 3) * 2;
            float b0 = bias[col], b1 = bias[col + 1];
            if (MODE == 0) {
                float2 v0 = { acc[mi][ni][0] + b0, acc[mi][ni][1] + b1 };
                float2 v1 = { acc[mi][ni][2] + b0, acc[mi][ni][3] + b1 };
                *(float2*)(Cf + (size_t)row * Dq + col)       = v0;
                *(float2*)(Cf + (size_t)(row + 8) * Dq + col) = v1;
            } else {
                float v0 = (acc[mi][ni][0] + b0) * scale;
                float v1 = (acc[mi][ni][1] + b1) * scale;
                float v2 = (acc[mi][ni][2] + b0) * scale;
                float v3 = (acc[mi][ni][3] + b1) * scale;
                __nv_bfloat16 h0 = __float2bfloat16(v0), h1 = __float2bfloat16(v1);
                __nv_bfloat16 h2 = __float2bfloat16(v2), h3 = __float2bfloat16(v3);
                *(__nv_bfloat162*)(Chi + (size_t)row * Dq + col)       = __halves2bfloat162(h0, h1);
                *(__nv_bfloat162*)(Chi + (size_t)(row + 8) * Dq + col) = __halves2bfloat162(h2, h3);
                *(__nv_bfloat162*)(Clo + (size_t)row * Dq + col) =
                    __halves2bfloat162(__float2bfloat16(v0 - __bfloat162float(h0)),
                                       __float2bfloat16(v1 - __bfloat162float(h1)));
                *(__nv_bfloat162*)(Clo + (size_t)(row + 8) * Dq + col) =
                    __halves2bfloat162(__float2bfloat16(v2 - __bfloat162float(h2)),
                                       __float2bfloat16(v3 - __bfloat162float(h3)));
            }
        }
    }
}

// ---------------------------------------------------------------------------
// Tensor-core flash attention (causal), register-repacked P, double-buffered KV.
// CTA: 128 q rows x (b,h). smem: Qh 18KB + 2 x (Kh|Kl|Vh|Vl 36KB) = 90KB.
// ---------------------------------------------------------------------------
#define ATT_SMEM (18432 + 2 * 36864)

__global__ void __launch_bounds__(256, 2)
attn_mma(const __nv_bfloat16* __restrict__ Qh_g, const __nv_bfloat16* __restrict__ Ql_g,
         const __nv_bfloat16* __restrict__ Kh_g, const __nv_bfloat16* __restrict__ Kl_g,
         const __nv_bfloat16* __restrict__ Vh_g, const __nv_bfloat16* __restrict__ Vl_g,
         __nv_bfloat16* __restrict__ AOh_g, __nv_bfloat16* __restrict__ AOl_g)
{
    extern __shared__ char smc[];
    const uint32_t smb = smem_u32(smc);
    const int t = threadIdx.x, lane = t & 31, w = t >> 5;
    const int qt = blockIdx.x;
    const int b = blockIdx.y >> 4, h = blockIdx.y & 15;
    const size_t row0 = (size_t)b * Tq + qt * 128;

    const uint32_t SQH = smb;                 // 128 x 144B
    const uint32_t SKV = smb + 18432;         // 2 bufs x (KH|KL|VH|VL, 9216 each)

    // ---- prologue: Qh -> SQH, Ql staged into KV buf0
#pragma unroll
    for (int i = 0; i < 4; ++i) {
        int idx = t + i * 256, r = idx >> 3, s = idx & 7;
        size_t g = (row0 + r) * Dq + h * 64 + s * 8;
        cp_async16(SQH + r * 144 + s * 16, Qh_g + g);
        cp_async16(SKV + r * 144 + s * 16, Ql_g + g);
    }
    asm volatile("cp.async.commit_group;" ::: "memory");
    asm volatile("cp.async.wait_group 0;" ::: "memory");
    __syncthreads();

    const uint32_t arow = w * 16 + (lane & 15);
    const uint32_t aco  = (lane >> 4) * 8;
    uint32_t ql[4][4];
#pragma unroll
    for (int ks = 0; ks < 4; ++ks)
        ldsm_x4(ql[ks], SKV + arow * 144 + (ks * 16 + aco) * 2);
    __syncthreads();

    auto issue_kv = [&](int jt) {
        const uint32_t kb = SKV + (uint32_t)(jt & 1) * 36864;
#pragma unroll
        for (int i = 0; i < 8; ++i) {
            int idx = t + i * 256;
            int mat = idx >> 9, rem = idx & 511, r = rem >> 3, s = rem & 7;
            const __nv_bfloat16* src = (mat == 0) ? Kh_g : (mat == 1) ? Kl_g
                                     : (mat == 2) ? Vh_g : Vl_g;
            size_t g = ((size_t)b * Tq + jt * 64 + r) * Dq + h * 64 + s * 8;
            cp_async16(kb + mat * 9216 + r * 144 + s * 16, src + g);
        }
        asm volatile("cp.async.commit_group;" ::: "memory");
    };

    float m0 = -1e30f, m1 = -1e30f, l0 = 0.f, l1 = 0.f;
    float oac[8][4];
#pragma unroll
    for (int ng = 0; ng < 8; ++ng)
#pragma unroll
        for (int k = 0; k < 4; ++k) oac[ng][k] = 0.f;

    const uint32_t krow = ((lane >> 4) & 1) * 8 + (lane & 7);
    const uint32_t kco  = ((lane >> 3) & 1) * 8;
    const uint32_t vrow = ((lane >> 3) & 1) * 8 + (lane & 7);
    const uint32_t vco  = ((lane >> 4) & 1) * 8;

    const int jtmax = 2 * qt + 1;
    issue_kv(0);

    for (int jt = 0; jt <= jtmax; ++jt) {
        if (jt + 1 <= jtmax) {
            issue_kv(jt + 1);
            asm volatile("cp.async.wait_group 1;" ::: "memory");
        } else {
            asm volatile("cp.async.wait_group 0;" ::: "memory");
        }
        __syncthreads();

        const uint32_t SKH = SKV + (uint32_t)(jt & 1) * 36864;
        const uint32_t SKL = SKH + 9216, SVH = SKH + 18432, SVL = SKH + 27648;

        // ---- S = Q @ K^T (3-pass split)
        float sac[8][4];
#pragma unroll
        for (int ng = 0; ng < 8; ++ng)
#pragma unroll
            for (int k = 0; k < 4; ++k) sac[ng][k] = 0.f;

#pragma unroll
        for (int ks = 0; ks < 4; ++ks) {
            uint32_t qh[4];
            ldsm_x4(qh, SQH + arow * 144 + (ks * 16 + aco) * 2);
            uint32_t kb[4][4];
#pragma unroll
            for (int g = 0; g < 4; ++g)
                ldsm_x4(kb[g], SKH + (g * 16 + krow) * 144 + (ks * 16 + kco) * 2);
#pragma unroll
            for (int g = 0; g < 4; ++g) {
                mma16816(sac[2*g],   qh,     kb[g][0], kb[g][1]);
                mma16816(sac[2*g+1], qh,     kb[g][2], kb[g][3]);
                mma16816(sac[2*g],   ql[ks], kb[g][0], kb[g][1]);
                mma16816(sac[2*g+1], ql[ks], kb[g][2], kb[g][3]);
            }
#pragma unroll
            for (int g = 0; g < 4; ++g)
                ldsm_x4(kb[g], SKL + (g * 16 + krow) * 144 + (ks * 16 + kco) * 2);
#pragma unroll
            for (int g = 0; g < 4; ++g) {
                mma16816(sac[2*g],   qh, kb[g][0], kb[g][1]);
                mma16816(sac[2*g+1], qh, kb[g][2], kb[g][3]);
            }
        }

        // ---- causal mask
        if (jt >= 2 * qt) {
            int q0 = qt * 128 + w * 16 + (lane >> 2);
#pragma unroll
            for (int ng = 0; ng < 8; ++ng) {
                int k0 = jt * 64 + ng * 8 + (lane & 3) * 2;
                if (k0     > q0)     sac[ng][0] = -1e30f;
                if (k0 + 1 > q0)     sac[ng][1] = -1e30f;
                if (k0     > q0 + 8) sac[ng][2] = -1e30f;
                if (k0 + 1 > q0 + 8) sac[ng][3] = -1e30f;
            }
        }

        // ---- online softmax (P stays in registers)
        float mx0 = -1e30f, mx1 = -1e30f;
#pragma unroll
        for (int ng = 0; ng < 8; ++ng) {
            mx0 = fmaxf(mx0, fmaxf(sac[ng][0], sac[ng][1]));
            mx1 = fmaxf(mx1, fmaxf(sac[ng][2], sac[ng][3]));
        }
        mx0 = fmaxf(mx0, __shfl_xor_sync(0xffffffffu, mx0, 1));
        mx0 = fmaxf(mx0, __shfl_xor_sync(0xffffffffu, mx0, 2));
        mx1 = fmaxf(mx1, __shfl_xor_sync(0xffffffffu, mx1, 1));
        mx1 = fmaxf(mx1, __shfl_xor_sync(0xffffffffu, mx1, 2));
        float mn0 = fmaxf(m0, mx0), mn1 = fmaxf(m1, mx1);
        float a0 = __expf(m0 - mn0), a1 = __expf(m1 - mn1);
        m0 = mn0; m1 = mn1;

        float rs0 = 0.f, rs1 = 0.f;
#pragma unroll
        for (int ng = 0; ng < 8; ++ng) {
            sac[ng][0] = __expf(sac[ng][0] - mn0);
            sac[ng][1] = __expf(sac[ng][1] - mn0);
            sac[ng][2] = __expf(sac[ng][2] - mn1);
            sac[ng][3] = __expf(sac[ng][3] - mn1);
            rs0 += sac[ng][0] + sac[ng][1];
            rs1 += sac[ng][2] + sac[ng][3];
        }
        rs0 += __shfl_xor_sync(0xffffffffu, rs0, 1);
        rs0 += __shfl_xor_sync(0xffffffffu, rs0, 2);
        rs1 += __shfl_xor_sync(0xffffffffu, rs1, 1);
        rs1 += __shfl_xor_sync(0xffffffffu, rs1, 2);
        l0 = l0 * a0 + rs0; l1 = l1 * a1 + rs1;
#pragma unroll
        for (int ng = 0; ng < 8; ++ng) {
            oac[ng][0] *= a0; oac[ng][1] *= a0;
            oac[ng][2] *= a1; oac[ng][3] *= a1;
        }

        // ---- O += P @ V  (P A-frags repacked from C-frags in registers)
#pragma unroll
        for (int ks = 0; ks < 4; ++ks) {
            const float* p0 = sac[2*ks];
            const float* p1 = sac[2*ks+1];
            uint32_t ph[4], pl[4];
            ph[0] = pack_bf16x2(p0[0], p0[1]);
            ph[1] = pack_bf16x2(p0[2], p0[3]);
            ph[2] = pack_bf16x2(p1[0], p1[1]);
            ph[3] = pack_bf16x2(p1[2], p1[3]);
            {
                __nv_bfloat162 t0 = *(__nv_bfloat162*)&ph[0];
                __nv_bfloat162 t1 = *(__nv_bfloat162*)&ph[1];
                __nv_bfloat162 t2 = *(__nv_bfloat162*)&ph[2];
                __nv_bfloat162 t3 = *(__nv_bfloat162*)&ph[3];
                pl[0] = pack_bf16x2(p0[0] - __bfloat162float(t0.x), p0[1] - __bfloat162float(t0.y));
                pl[1] = pack_bf16x2(p0[2] - __bfloat162float(t1.x), p0[3] - __bfloat162float(t1.y));
                pl[2] = pack_bf16x2(p1[0] - __bfloat162float(t2.x), p1[1] - __bfloat162float(t2.y));
                pl[3] = pack_bf16x2(p1[2] - __bfloat162float(t3.x), p1[3] - __bfloat162float(t3.y));
            }
#pragma unroll
            for (int g = 0; g < 4; ++g) {
                uint32_t vb[4];
                ldsm_x4_t(vb, SVH + (ks * 16 + vrow) * 144 + (g * 16 + vco) * 2);
                mma16816(oac[2*g],   ph, vb[0], vb[1]);
                mma16816(oac[2*g+1], ph, vb[2], vb[3]);
                mma16816(oac[2*g],   pl, vb[0], vb[1]);
                mma16816(oac[2*g+1], pl, vb[2], vb[3]);
                ldsm_x4_t(vb, SVL + (ks * 16 + vrow) * 144 + (g * 16 + vco) * 2);
                mma16816(oac[2*g],   ph, vb[0], vb[1]);
                mma16816(oac[2*g+1], ph, vb[2], vb[3]);
            }
        }
        __syncthreads();   // KV buf reads done before it is overwritten
    }

    // ---- epilogue
    float i0 = 1.f / l0, i1 = 1.f / l1;
    size_t gr0 = row0 + w * 16 + (lane >> 2);
#pragma unroll
    for (int ng = 0; ng < 8; ++ng) {
        int col = h * 64 + ng * 8 + (lane & 3) * 2;
        float v0 = oac[ng][0] * i0, v1 = oac[ng][1] * i0;
        float v2 = oac[ng][2] * i1, v3 = oac[ng][3] * i1;
        __nv_bfloat16 h0 = __float2bfloat16(v0), h1 = __float2bfloat16(v1);
        __nv_bfloat16 h2 = __float2bfloat16(v2), h3 = __float2bfloat16(v3);
        *(__nv_bfloat162*)(AOh_g + gr0 * Dq + col)       = __halves2bfloat162(h0, h1);
        *(__nv_bfloat162*)(AOh_g + (gr0 + 8) * Dq + col) = __halves2bfloat162(h2, h3);
        *(__nv_bfloat162*)(AOl_g + gr0 * Dq + col) =
            __halves2bfloat162(__float2bfloat16(v0 - __bfloat162float(h0)),
                               __float2bfloat16(v1 - __bfloat162float(h1)));
        *(__nv_bfloat162*)(AOl_g + (gr0 + 8) * Dq + col) =
            __halves2bfloat162(__float2bfloat16(v2 - __bfloat162float(h2)),
                               __float2bfloat16(v3 - __bfloat162float(h3)));
    }
}

// ---------------------------------------------------------------------------
extern "C" void kernel_launch(void* const* d_in, const int* in_sizes, int n_in,
                              void* d_out, int out_size)
{
    const float* x  = (const float*)d_in[0];
    const float* Wq = (const float*)d_in[2];
    const float* bq = (const float*)d_in[3];
    const float* Wk = (const float*)d_in[4];
    const float* bk = (const float*)d_in[5];
    const float* Wv = (const float*)d_in[6];
    const float* bv = (const float*)d_in[7];
    const float* Wo = (const float*)d_in[8];
    const float* bo = (const float*)d_in[9];
    float* out = (float*)d_out;

    __nv_bfloat16 *ahi, *alo, *whi, *wlo;
    __nv_bfloat16 *qh, *qlp, *kh, *kl, *vh, *vl, *aoh, *aol;
    cudaGetSymbolAddress((void**)&ahi, g_Ahi);
    cudaGetSymbolAddress((void**)&alo, g_Alo);
    cudaGetSymbolAddress((void**)&whi, g_Whi);
    cudaGetSymbolAddress((void**)&wlo, g_Wlo);
    cudaGetSymbolAddress((void**)&qh,  g_Qh);
    cudaGetSymbolAddress((void**)&qlp, g_Ql);
    cudaGetSymbolAddress((void**)&kh,  g_Kh);
    cudaGetSymbolAddress((void**)&kl,  g_Kl);
    cudaGetSymbolAddress((void**)&vh,  g_Vh);
    cudaGetSymbolAddress((void**)&vl,  g_Vl);
    cudaGetSymbolAddress((void**)&aoh, g_AOh);
    cudaGetSymbolAddress((void**)&aol, g_AOl);

    cudaFuncSetAttribute(gemm_mma<0>, cudaFuncAttributeMaxDynamicSharedMemorySize, GEMM_SMEM);
    cudaFuncSetAttribute(gemm_mma<1>, cudaFuncAttributeMaxDynamicSharedMemorySize, GEMM_SMEM);
    cudaFuncSetAttribute(attn_mma, cudaFuncAttributeMaxDynamicSharedMemorySize, ATT_SMEM);

    const int NPROJ = Mq * Dq;
    dim3 tsg(32, 32), tsb(32, 8);
    dim3 ggrid(Dq / 128, Mq / 128);

    split_kernel<<<NPROJ / 1024, 256>>>(x, ahi, alo, NPROJ);
    const float* Ws[4] = { Wq, Wk, Wv, Wo };
    for (int w = 0; w < 4; ++w)
        transpose_split_kernel<<<tsg, tsb>>>(Ws[w], whi + (size_t)w * Dq * Dq,
                                             wlo + (size_t)w * Dq * Dq);

    gemm_mma<1><<<ggrid, 256, GEMM_SMEM>>>(ahi, alo, whi, wlo, bq, 0.125f,
                                           nullptr, qh, qlp);
    gemm_mma<1><<<ggrid, 256, GEMM_SMEM>>>(ahi, alo, whi + (size_t)Dq * Dq,
                                           wlo + (size_t)Dq * Dq, bk, 1.f,
                                           nullptr, kh, kl);
    gemm_mma<1><<<ggrid, 256, GEMM_SMEM>>>(ahi, alo, whi + 2 * (size_t)Dq * Dq,
                                           wlo + 2 * (size_t)Dq * Dq, bv, 1.f,
                                           nullptr, vh, vl);

    dim3 agrid(Tq / 128, Bq * Hq);
    attn_mma<<<agrid, 256, ATT_SMEM>>>(qh, qlp, kh, kl, vh, vl, aoh, aol);

    gemm_mma<0><<<ggrid, 256, GEMM_SMEM>>>(aoh, aol, whi + 3 * (size_t)Dq * Dq,
                                           wlo + 3 * (size_t)Dq * Dq, bo, 1.f,
                                           out, nullptr, nullptr);
}